// round 9
// baseline (speedup 1.0000x reference)
#include <cuda_runtime.h>

// WaveletDWTLayer — PURE STREAMING version: no smem, no __syncthreads.
// One thread per coefficient index i (2048 per row). Each thread:
//   - loads its x1 window ext[2i..2i+17] (overlaps neighbors -> L1 hits)
//   - computes cA[i], cD[i..i+5] (local recompute, FFMA-imm rate 1)
//   - computes R[4i..4i+3] = idwt(a, x2) with a = idwt(0,cD) on the fly
//   - writes cA, cDs(ch0 = x2 copy, ch1 = cD + FILLER), R directly to gmem
// Outputs concatenated: cA [B,1,2051] | cDs [B,2,1,4096] | R [B,1,1,8186]

namespace {
constexpr int L    = 4096;
constexpr int NC   = 2051;         // (L+7)/2
constexpr int RLEN = 2 * L - 6;    // 8186

// REC_LO (analysis filter in reference's conv — lax conv = cross-correlation)
__device__ constexpr float RLO[8] = {
     0.23037781330885523f,  0.7148465705525415f,   0.6308807679295904f,  -0.02798376941698385f,
    -0.18703481171888114f,  0.030841381835986965f, 0.032883011666982945f,-0.010597401784997278f};
// REC_HI[k] = (-1)^k * REC_LO[7-k]
__device__ constexpr float RHI[8] = {
    -0.010597401784997278f,-0.032883011666982945f, 0.030841381835986965f, 0.18703481171888114f,
    -0.02798376941698385f, -0.6308807679295904f,   0.7148465705525415f,  -0.23037781330885523f};
// DEC_LO[k] = REC_LO[7-k]
__device__ constexpr float DLO[8] = {
    -0.010597401784997278f, 0.032883011666982945f, 0.030841381835986965f,-0.18703481171888114f,
    -0.02798376941698385f,  0.6308807679295904f,   0.7148465705525415f,   0.23037781330885523f};
// DEC_HI[k] = REC_HI[7-k]
__device__ constexpr float DHI[8] = {
    -0.23037781330885523f,  0.7148465705525415f,  -0.6308807679295904f,  -0.02798376941698385f,
     0.18703481171888114f,  0.030841381835986965f,-0.032883011666982945f,-0.010597401784997278f};
} // namespace

__global__ __launch_bounds__(256, 4)
void wavelet_stream_kernel(const float* __restrict__ x1,
                           const float* __restrict__ x2,
                           float* __restrict__ out, int B)
{
    const int b = blockIdx.y;
    const int i = blockIdx.x * 256 + threadIdx.x;   // 0..2047

    const float* __restrict__ x1row = x1 + (size_t)b * L;
    const float* __restrict__ x2row = x2 + (size_t)b * L;

    float* __restrict__ outA = out + (size_t)b * NC;
    float* __restrict__ outD = out + (size_t)B * NC + (size_t)b * (2 * L);
    float* __restrict__ outR = out + (size_t)B * NC + (size_t)B * (2 * L)
                                   + (size_t)b * RLEN;

    // ---- x1 window: w[c] = ext[2i + c], c = 0..17 ----
    // ext[j] = x1[5-j] (j<6) | x1[j-6] (6<=j<=L+5) | x1[2L+5-j] (j>L+5)
    float w[18];
    if (i >= 3 && i <= 2042) {                       // fast path: direct, 8B-aligned
        const float2* p = reinterpret_cast<const float2*>(x1row + 2 * i - 6);
#pragma unroll
        for (int c2 = 0; c2 < 9; c2++) {
            float2 v = p[c2];
            w[2 * c2]     = v.x;
            w[2 * c2 + 1] = v.y;
        }
    } else {                                         // edge path: reflect-mapped scalars
#pragma unroll
        for (int c = 0; c < 18; c++) {
            int j   = 2 * i + c;
            int src = (j < 6) ? (5 - j) : ((j <= L + 5) ? (j - 6) : (2 * L + 5 - j));
            w[c] = x1row[src];
        }
    }

    // ---- x2 window: b0..b4 = x2[2i .. 2i+4] (guarded at row end) ----
    const float2* q = reinterpret_cast<const float2*>(x2row + 2 * i);
    float2 q0 = q[0];
    float2 q1 = (i < 2047) ? q[1] : make_float2(0.f, 0.f);
    float  b4 = (i < 2046) ? x2row[2 * i + 4] : 0.f;

    // ---- cA[i] and cD[i .. i+5] ----
    float cA;
    {
        float s = w[0] * RLO[0];
#pragma unroll
        for (int k = 1; k < 8; k++) s = fmaf(w[k], RLO[k], s);
        cA = s;
    }
    float c[6];
#pragma unroll
    for (int j = 0; j < 6; j++) {
        float s = w[2 * j] * RHI[0];
#pragma unroll
        for (int k = 1; k < 8; k++) s = fmaf(w[2 * j + k], RHI[k], s);
        c[j] = s;
    }

    // ---- direct output writes (all streams, no staging) ----
    outA[i]     = cA;                                 // cA[i]
    outD[L + i] = c[0];                               // cDs ch1 = cD[i]
    *reinterpret_cast<float2*>(outD + 2 * i) = q0;    // cDs ch0 = x2 copy
    if (i >= 3) outD[L + 2048 + i] = 10.1f;           // FILLER (L+2051 .. L+4095)

    // ---- R quad v = i: a = idwt(0,cD) on the fly, then R = idwt(a, x2) ----
    if (i < 2047) {
        float ae0 = fmaf(c[0], DHI[1], fmaf(c[1], DHI[3], fmaf(c[2], DHI[5], c[3] * DHI[7])));
        float ao0 = fmaf(c[0], DHI[0], fmaf(c[1], DHI[2], fmaf(c[2], DHI[4], c[3] * DHI[6])));
        float ae1 = fmaf(c[1], DHI[1], fmaf(c[2], DHI[3], fmaf(c[3], DHI[5], c[4] * DHI[7])));
        float ao1 = fmaf(c[1], DHI[0], fmaf(c[2], DHI[2], fmaf(c[3], DHI[4], c[4] * DHI[6])));

        float e0 = fmaf(ae0, DLO[1], fmaf(ao0, DLO[3], fmaf(ae1, DLO[5], ao1 * DLO[7])));
        e0 = fmaf(q0.x, DHI[1], fmaf(q0.y, DHI[3], fmaf(q1.x, DHI[5], fmaf(q1.y, DHI[7], e0))));
        float o0 = fmaf(ae0, DLO[0], fmaf(ao0, DLO[2], fmaf(ae1, DLO[4], ao1 * DLO[6])));
        o0 = fmaf(q0.x, DHI[0], fmaf(q0.y, DHI[2], fmaf(q1.x, DHI[4], fmaf(q1.y, DHI[6], o0))));
        *reinterpret_cast<float2*>(outR + 4 * i) = make_float2(e0, o0);

        if (i < 2046) {     // pair u = 2i+1 -> R[4i+2], R[4i+3]
            float ae2 = fmaf(c[2], DHI[1], fmaf(c[3], DHI[3], fmaf(c[4], DHI[5], c[5] * DHI[7])));
            float e1 = fmaf(ao0, DLO[1], fmaf(ae1, DLO[3], fmaf(ao1, DLO[5], ae2 * DLO[7])));
            e1 = fmaf(q0.y, DHI[1], fmaf(q1.x, DHI[3], fmaf(q1.y, DHI[5], fmaf(b4, DHI[7], e1))));
            float o1 = fmaf(ao0, DLO[0], fmaf(ae1, DLO[2], fmaf(ao1, DLO[4], ae2 * DLO[6])));
            o1 = fmaf(q0.y, DHI[0], fmaf(q1.x, DHI[2], fmaf(q1.y, DHI[4], fmaf(b4, DHI[6], o1))));
            *reinterpret_cast<float2*>(outR + 4 * i + 2) = make_float2(e1, o1);
        }
    }

    // ---- tail extras: thread 2047 emits cA/cD[2048..2050] ----
    // cA[2048+m] = sum_k ext[4096+2m+k]*RLO[k] = sum_k w[2+2m+k]*RLO[k]  (2i = 4094)
    if (i == 2047) {
#pragma unroll
        for (int m = 0; m < 3; m++) {
            float sa = w[2 + 2 * m] * RLO[0];
            float sd = w[2 + 2 * m] * RHI[0];
#pragma unroll
            for (int k = 1; k < 8; k++) {
                sa = fmaf(w[2 + 2 * m + k], RLO[k], sa);
                sd = fmaf(w[2 + 2 * m + k], RHI[k], sd);
            }
            outA[2048 + m]     = sa;
            outD[L + 2048 + m] = sd;
        }
    }
}

extern "C" void kernel_launch(void* const* d_in, const int* in_sizes, int n_in,
                              void* d_out, int out_size) {
    const float* x1 = (const float*)d_in[0];   // [B,1,L]
    const float* x2 = (const float*)d_in[1];   // [B,1,1,L]
    // d_in[2] = x3 [B,1,1,1] is unused by the reference math.
    int B = in_sizes[2];                       // x3 has exactly B elements
    dim3 grid(8, B);                           // 8 x 256 = 2048 threads per row
    wavelet_stream_kernel<<<grid, 256>>>(x1, x2, (float*)d_out, B);
}

// round 10
// speedup vs baseline: 1.1406x; 1.1406x over previous
#include <cuda_runtime.h>

// WaveletDWTLayer: fused db4 DWT + 2x IDWT, one CTA per batch row.
// Outputs concatenated: cA [B,1,2051] | cDs [B,2,1,4096] | R [B,1,1,8186]
// Phase-4 recomputes the intermediate `a` on the fly from cD (4-tap).
// All gmem traffic is touch-once => .cs (evict-first) load/store hints keep
// L2 from churning on dead write data and favor the read streams.

namespace {
constexpr int L    = 4096;         // signal length
constexpr int NC   = 2051;         // dwt coeff count = (L+7)/2
constexpr int EXT  = L + 13;       // symmetric-extended length (4109)
constexpr int RLEN = 2 * L - 6;    // final idwt output length (8186)
constexpr int NV   = RLEN / 4 + 1; // 2047 quad-groups (last is a half group)

// REC_LO (analysis filter in the reference's conv — lax conv = cross-correlation)
__device__ constexpr float RLO[8] = {
     0.23037781330885523f,  0.7148465705525415f,   0.6308807679295904f,  -0.02798376941698385f,
    -0.18703481171888114f,  0.030841381835986965f, 0.032883011666982945f,-0.010597401784997278f};
// REC_HI[k] = (-1)^k * REC_LO[7-k]
__device__ constexpr float RHI[8] = {
    -0.010597401784997278f,-0.032883011666982945f, 0.030841381835986965f, 0.18703481171888114f,
    -0.02798376941698385f, -0.6308807679295904f,   0.7148465705525415f,  -0.23037781330885523f};
// DEC_LO[k] = REC_LO[7-k]
__device__ constexpr float DLO[8] = {
    -0.010597401784997278f, 0.032883011666982945f, 0.030841381835986965f,-0.18703481171888114f,
    -0.02798376941698385f,  0.6308807679295904f,   0.7148465705525415f,   0.23037781330885523f};
// DEC_HI[k] = REC_HI[7-k]
__device__ constexpr float DHI[8] = {
    -0.23037781330885523f,  0.7148465705525415f,  -0.6308807679295904f,  -0.02798376941698385f,
     0.18703481171888114f,  0.030841381835986965f,-0.032883011666982945f,-0.010597401784997278f};
} // namespace

__global__ __launch_bounds__(256, 8)
void wavelet_fused_kernel(const float* __restrict__ x1,
                          const float* __restrict__ x2,
                          float* __restrict__ out, int B)
{
    __shared__ alignas(16) float s_x[EXT + 3];   // ext(x1), then x2 row (first L)
    __shared__ alignas(16) float s_cD[NC + 5];   // +pad so tail reads stay in-bounds

    const int b = blockIdx.x;
    const int t = threadIdx.x;

    const float* __restrict__ x1row = x1 + (size_t)b * L;
    const float* __restrict__ x2row = x2 + (size_t)b * L;

    float* __restrict__ outA = out + (size_t)b * NC;
    float* __restrict__ outD = out + (size_t)B * NC + (size_t)b * (2 * L);
    float* __restrict__ outR = out + (size_t)B * NC + (size_t)B * (2 * L)
                                   + (size_t)b * RLEN;

    // ---- Phase 1: symmetric-extended x1 into smem; FILLER tail of cDs ch1 ----
    // ext = [x5..x0 | x0..x_{L-1} | x_{L-1}..x_{L-7}]  (length L+13)
    for (int i4 = t; i4 < L / 4; i4 += 256) {       // body: float4 streaming loads
        float4 v = __ldcs(reinterpret_cast<const float4*>(x1row) + i4);
        int j = 6 + 4 * i4;
        s_x[j] = v.x; s_x[j + 1] = v.y; s_x[j + 2] = v.z; s_x[j + 3] = v.w;
    }
    if (t < 6)            s_x[t]     = __ldcs(x1row + 5 - t);      // head: x5..x0
    else if (t < 13)      s_x[L + t] = __ldcs(x1row + L + 5 - t);  // tail: x_{L-1}..x_{L-7}
    else if (t == 13) { s_cD[NC] = 0.f; s_cD[NC + 1] = 0.f; }      // cD pad
    for (int i = NC + t; i < L; i += 256) __stcs(outD + L + i, 10.1f);  // FILLER
    __syncthreads();

    // ---- Phase 2: DWT (stride-2, 8-tap), float2 smem reads ----
    {
        const float2* s_p = reinterpret_cast<const float2*>(s_x);
        for (int i = t; i < NC; i += 256) {
            float2 p0 = s_p[i], p1 = s_p[i + 1], p2 = s_p[i + 2], p3 = s_p[i + 3];
            float lo, hi;
            lo = fmaf(p0.x, RLO[0], p0.y * RLO[1]);
            lo = fmaf(p1.x, RLO[2], fmaf(p1.y, RLO[3], lo));
            lo = fmaf(p2.x, RLO[4], fmaf(p2.y, RLO[5], lo));
            lo = fmaf(p3.x, RLO[6], fmaf(p3.y, RLO[7], lo));
            hi = fmaf(p0.x, RHI[0], p0.y * RHI[1]);
            hi = fmaf(p1.x, RHI[2], fmaf(p1.y, RHI[3], hi));
            hi = fmaf(p2.x, RHI[4], fmaf(p2.y, RHI[5], hi));
            hi = fmaf(p3.x, RHI[6], fmaf(p3.y, RHI[7], hi));
            __stcs(outA + i, lo);
            s_cD[i] = hi;
            __stcs(outD + L + i, hi);        // cDs channel 1
        }
    }
    __syncthreads();

    // ---- Phase 3: overwrite s_x with x2 row; copy x2 -> cDs ch 0 ----
    for (int i4 = t; i4 < L / 4; i4 += 256) {
        float4 v = __ldcs(reinterpret_cast<const float4*>(x2row) + i4);
        reinterpret_cast<float4*>(s_x)[i4] = v;
        __stcs(reinterpret_cast<float4*>(outD) + i4, v);
    }
    __syncthreads();

    // ---- Phase 4: R = idwt(a, x2) with a = idwt(0, cD) recomputed on the fly ----
    // a[2v+s] are 4-tap combos of cD[v..v+5]; R quad (4v..4v+3) = pairs u=2v, 2v+1.
    // Even outputs use taps {1,3,5,7}, odd use {0,2,4,6}; no boundary clipping.
    for (int v = t; v < NV; v += 256) {
        float c0 = s_cD[v],     c1 = s_cD[v + 1], c2 = s_cD[v + 2];
        float c3 = s_cD[v + 3], c4 = s_cD[v + 4], c5 = s_cD[v + 5];

        float ae0 = fmaf(c0, DHI[1], fmaf(c1, DHI[3], fmaf(c2, DHI[5], c3 * DHI[7])));
        float ao0 = fmaf(c0, DHI[0], fmaf(c1, DHI[2], fmaf(c2, DHI[4], c3 * DHI[6])));
        float ae1 = fmaf(c1, DHI[1], fmaf(c2, DHI[3], fmaf(c3, DHI[5], c4 * DHI[7])));
        float ao1 = fmaf(c1, DHI[0], fmaf(c2, DHI[2], fmaf(c3, DHI[4], c4 * DHI[6])));

        float b0 = s_x[2 * v],     b1 = s_x[2 * v + 1], b2 = s_x[2 * v + 2];
        float b3 = s_x[2 * v + 3], b4 = s_x[2 * v + 4];

        // pair u = 2v  -> R[4v], R[4v+1]
        float e0 = fmaf(ae0, DLO[1], fmaf(ao0, DLO[3], fmaf(ae1, DLO[5], ao1 * DLO[7])));
        e0 = fmaf(b0, DHI[1], fmaf(b1, DHI[3], fmaf(b2, DHI[5], fmaf(b3, DHI[7], e0))));
        float o0 = fmaf(ae0, DLO[0], fmaf(ao0, DLO[2], fmaf(ae1, DLO[4], ao1 * DLO[6])));
        o0 = fmaf(b0, DHI[0], fmaf(b1, DHI[2], fmaf(b2, DHI[4], fmaf(b3, DHI[6], o0))));
        __stcs(reinterpret_cast<float2*>(outR + 4 * v), make_float2(e0, o0));

        if (v < NV - 1) {   // pair u = 2v+1 -> R[4v+2], R[4v+3] (absent in last group)
            float ae2 = fmaf(c2, DHI[1], fmaf(c3, DHI[3], fmaf(c4, DHI[5], c5 * DHI[7])));
            float e1 = fmaf(ao0, DLO[1], fmaf(ae1, DLO[3], fmaf(ao1, DLO[5], ae2 * DLO[7])));
            e1 = fmaf(b1, DHI[1], fmaf(b2, DHI[3], fmaf(b3, DHI[5], fmaf(b4, DHI[7], e1))));
            float o1 = fmaf(ao0, DLO[0], fmaf(ae1, DLO[2], fmaf(ao1, DLO[4], ae2 * DLO[6])));
            o1 = fmaf(b1, DHI[0], fmaf(b2, DHI[2], fmaf(b3, DHI[4], fmaf(b4, DHI[6], o1))));
            __stcs(reinterpret_cast<float2*>(outR + 4 * v + 2), make_float2(e1, o1));
        }
    }
}

extern "C" void kernel_launch(void* const* d_in, const int* in_sizes, int n_in,
                              void* d_out, int out_size) {
    const float* x1 = (const float*)d_in[0];   // [B,1,L]
    const float* x2 = (const float*)d_in[1];   // [B,1,1,L]
    // d_in[2] = x3 [B,1,1,1] is unused by the reference math.
    int B = in_sizes[2];                       // x3 has exactly B elements
    wavelet_fused_kernel<<<B, 256>>>(x1, x2, (float*)d_out, B);
}